// round 16
// baseline (speedup 1.0000x reference)
#include <cuda_runtime.h>
#include <cuda_bf16.h>
#include <math.h>
#include <cstdint>

#define SQ   1024
#define DM   1024
#define NH   16
#define HD   64
#define NB   4
#define BH   (NB*NH)
#define ER_L 2049

// ---------------------------------------------------------------------------
// Device scratch: projected q,k,v stored directly as bf16 hi/lo pairs.
// ---------------------------------------------------------------------------
__device__ __nv_bfloat16 g_qh[(size_t)BH * SQ * HD], g_ql[(size_t)BH * SQ * HD];
__device__ __nv_bfloat16 g_kh[(size_t)BH * SQ * HD], g_kl[(size_t)BH * SQ * HD];
__device__ __nv_bfloat16 g_vh[(size_t)BH * SQ * HD], g_vl[(size_t)BH * SQ * HD];

__device__ __nv_bfloat16 g_xh[3][(size_t)NB * SQ * DM];   // inputs hi
__device__ __nv_bfloat16 g_xl[3][(size_t)NB * SQ * DM];   // inputs lo
__device__ __nv_bfloat16 g_wh[3][(size_t)DM * DM];        // weights hi
__device__ __nv_bfloat16 g_wl[3][(size_t)DM * DM];        // weights lo

__device__ __nv_bfloat16 g_erh[(size_t)NH * ER_L * HD];   // Er hi
__device__ __nv_bfloat16 g_erl[(size_t)NH * ER_L * HD];   // Er lo

__device__ float g_rowsum[(size_t)BH * SQ];               // softmax denominators

// ---------------------------------------------------------------------------
// mma.sync + cp.async helpers
// ---------------------------------------------------------------------------
__device__ __forceinline__ uint32_t smem_u32(const void* p) {
    uint32_t a;
    asm("{ .reg .u64 t; cvta.to.shared.u64 t, %1; cvt.u32.u64 %0, t; }"
        : "=r"(a) : "l"(p));
    return a;
}
__device__ __forceinline__ void ldsm_x4(uint32_t (&r)[4], uint32_t addr) {
    asm volatile("ldmatrix.sync.aligned.m8n8.x4.shared.b16 {%0,%1,%2,%3}, [%4];"
                 : "=r"(r[0]), "=r"(r[1]), "=r"(r[2]), "=r"(r[3]) : "r"(addr));
}
__device__ __forceinline__ void mma_bf16(float (&c)[4], const uint32_t (&a)[4],
                                         const uint32_t b0, const uint32_t b1) {
    asm volatile("mma.sync.aligned.m16n8k16.row.col.f32.bf16.bf16.f32 "
                 "{%0,%1,%2,%3}, {%4,%5,%6,%7}, {%8,%9}, {%0,%1,%2,%3};"
                 : "+f"(c[0]), "+f"(c[1]), "+f"(c[2]), "+f"(c[3])
                 : "r"(a[0]), "r"(a[1]), "r"(a[2]), "r"(a[3]), "r"(b0), "r"(b1));
}
#define CP_ASYNC16(smem, gptr) \
    asm volatile("cp.async.cg.shared.global [%0], [%1], 16;" \
                 :: "r"(smem), "l"(gptr) : "memory")
#define CP_COMMIT() asm volatile("cp.async.commit_group;" ::: "memory")
#define CP_WAIT(n)  asm volatile("cp.async.wait_group %0;" :: "n"(n) : "memory")

__device__ __forceinline__ void f4_to_hilo(float4 v, uint2& H, uint2& L) {
    union { __nv_bfloat16 b[4]; uint2 u; } hh, ll;
    hh.b[0] = __float2bfloat16(v.x);
    hh.b[1] = __float2bfloat16(v.y);
    hh.b[2] = __float2bfloat16(v.z);
    hh.b[3] = __float2bfloat16(v.w);
    ll.b[0] = __float2bfloat16(v.x - __bfloat162float(hh.b[0]));
    ll.b[1] = __float2bfloat16(v.y - __bfloat162float(hh.b[1]));
    ll.b[2] = __float2bfloat16(v.z - __bfloat162float(hh.b[2]));
    ll.b[3] = __float2bfloat16(v.w - __bfloat162float(hh.b[3]));
    H = hh.u; L = ll.u;
}

// ---------------------------------------------------------------------------
// fp32 -> bf16 hi/lo splits (all six q/k/v/Wq/Wk/Wv in one launch)
// ---------------------------------------------------------------------------
#define XN4 (NB * SQ * DM / 4)     // 1048576 float4 per input tensor
#define WN4 (DM * DM / 4)          // 262144 float4 per weight tensor
#define SPLIT_TOTAL (3 * XN4 + 3 * WN4)

__global__ __launch_bounds__(256)
void split_all_kernel(const float* __restrict__ q, const float* __restrict__ k,
                      const float* __restrict__ v, const float* __restrict__ wq,
                      const float* __restrict__ wk, const float* __restrict__ wv) {
    int i = blockIdx.x * blockDim.x + threadIdx.x;
    if (i >= SPLIT_TOTAL) return;
    const float* src;
    __nv_bfloat16 *hi, *lo;
    int off;
    if (i < 3 * XN4) {
        int which = i / XN4;
        off = i - which * XN4;
        src = (which == 0) ? q : (which == 1) ? k : v;
        hi = g_xh[which]; lo = g_xl[which];
    } else {
        int j = i - 3 * XN4;
        int which = j / WN4;
        off = j - which * WN4;
        src = (which == 0) ? wq : (which == 1) ? wk : wv;
        hi = g_wh[which]; lo = g_wl[which];
    }
    float4 vv = reinterpret_cast<const float4*>(src)[off];
    uint2 H, L;
    f4_to_hilo(vv, H, L);
    reinterpret_cast<uint2*>(hi)[off] = H;
    reinterpret_cast<uint2*>(lo)[off] = L;
}

__global__ __launch_bounds__(256)
void er_split_kernel(const float* __restrict__ Er, int n4) {
    int i = blockIdx.x * blockDim.x + threadIdx.x;
    if (i >= n4) return;
    float4 v = reinterpret_cast<const float4*>(Er)[i];
    uint2 H, L;
    f4_to_hilo(v, H, L);
    reinterpret_cast<uint2*>(g_erh)[i] = H;
    reinterpret_cast<uint2*>(g_erl)[i] = L;
}

__global__ __launch_bounds__(1024)
void zero_rowsum_kernel() {
    g_rowsum[blockIdx.x * 1024 + threadIdx.x] = 0.f;
}

// ---------------------------------------------------------------------------
// Projection GEMM on mma.sync; cp.async double-buffered; 3 projections in
// one launch (blockIdx.z selects q/k/v); epilogue writes bf16 hi/lo.
// ---------------------------------------------------------------------------
#define PROW 40
#define P_PLANE (128 * PROW)              // bf16 elements per plane
#define P_SMEM  (2 * 4 * P_PLANE * 2)     // 81920 bytes

__global__ __launch_bounds__(256, 1)
void proj_mma_kernel(const float* __restrict__ bq,
                     const float* __restrict__ bk,
                     const float* __restrict__ bv) {
    extern __shared__ __nv_bfloat16 psm[];   // [2][4][128*PROW]

    const int which = blockIdx.z;
    const float* bias = (which == 0) ? bq : (which == 1) ? bk : bv;
    const __nv_bfloat16* Ah = g_xh[which];
    const __nv_bfloat16* Al = g_xl[which];
    const __nv_bfloat16* Bh = g_wh[which];
    const __nv_bfloat16* Bl = g_wl[which];
    __nv_bfloat16* oh = (which == 0) ? g_qh : (which == 1) ? g_kh : g_vh;
    __nv_bfloat16* ol = (which == 0) ? g_ql : (which == 1) ? g_kl : g_vl;

    const int tid = threadIdx.x;
    const int wid = tid >> 5;
    const int lid = tid & 31;
    const int wm = wid & 1;
    const int wn = wid >> 1;
    const int m0 = blockIdx.y * 128;
    const int n0 = blockIdx.x * 128;

    const int a_row = (lid & 7) + ((lid >> 3) & 1) * 8;
    const int a_kh  = (lid >= 16) ? 8 : 0;
    const int b_n   = (lid & 7) + ((lid >= 16) ? 8 : 0);
    const int b_kh  = ((lid >> 3) & 1) * 8;

    const uint32_t sbase = smem_u32(psm);

    float acc[4][4][4] = {};

    auto load_chunk = [&](int c, int buf) {
        const int k0g = c * 32;
        #pragma unroll
        for (int p = 0; p < 4; ++p) {
            const __nv_bfloat16* g = (p == 0) ? Ah : (p == 1) ? Al
                                    : (p == 2) ? Bh : Bl;
            const int rbase = (p < 2) ? m0 : n0;
            #pragma unroll
            for (int it = 0; it < 2; ++it) {
                int idx = tid + it * 256;        // 0..511
                int r = idx >> 2, seg = idx & 3; // seg: 8 bf16 = 16 B
                uint32_t dst = sbase +
                    (uint32_t)(((buf * 4 + p) * P_PLANE + r * PROW + seg * 8) * 2);
                CP_ASYNC16(dst, g + (size_t)(rbase + r) * DM + k0g + seg * 8);
            }
        }
        CP_COMMIT();
    };

    load_chunk(0, 0);

    const int NCH = DM / 32;
    for (int c = 0; c < NCH; ++c) {
        const int buf = c & 1;
        if (c + 1 < NCH) { load_chunk(c + 1, (c + 1) & 1); CP_WAIT(1); }
        else             { CP_WAIT(0); }
        __syncthreads();

        const uint32_t sA_h = sbase + (uint32_t)((buf * 4 + 0) * P_PLANE * 2);
        const uint32_t sA_l = sbase + (uint32_t)((buf * 4 + 1) * P_PLANE * 2);
        const uint32_t sB_h = sbase + (uint32_t)((buf * 4 + 2) * P_PLANE * 2);
        const uint32_t sB_l = sbase + (uint32_t)((buf * 4 + 3) * P_PLANE * 2);

        #pragma unroll
        for (int ks = 0; ks < 2; ++ks) {
            const int k0 = ks * 16;
            uint32_t fAh[4][4], fAl[4][4], fBh[4][2], fBl[4][2];
            #pragma unroll
            for (int mi = 0; mi < 4; ++mi) {
                uint32_t off = (uint32_t)(((wm * 64 + mi * 16 + a_row) * PROW
                                           + k0 + a_kh) * 2);
                ldsm_x4(fAh[mi], sA_h + off);
                ldsm_x4(fAl[mi], sA_l + off);
            }
            #pragma unroll
            for (int pp = 0; pp < 2; ++pp) {
                uint32_t off = (uint32_t)(((wn * 32 + pp * 16 + b_n) * PROW
                                           + k0 + b_kh) * 2);
                uint32_t t[4];
                ldsm_x4(t, sB_h + off);
                fBh[pp * 2][0] = t[0]; fBh[pp * 2][1] = t[1];
                fBh[pp * 2 + 1][0] = t[2]; fBh[pp * 2 + 1][1] = t[3];
                ldsm_x4(t, sB_l + off);
                fBl[pp * 2][0] = t[0]; fBl[pp * 2][1] = t[1];
                fBl[pp * 2 + 1][0] = t[2]; fBl[pp * 2 + 1][1] = t[3];
            }
            #pragma unroll
            for (int mi = 0; mi < 4; ++mi)
                #pragma unroll
                for (int ni = 0; ni < 4; ++ni) {
                    mma_bf16(acc[mi][ni], fAh[mi], fBh[ni][0], fBh[ni][1]);
                    mma_bf16(acc[mi][ni], fAh[mi], fBl[ni][0], fBl[ni][1]);
                    mma_bf16(acc[mi][ni], fAl[mi], fBh[ni][0], fBh[ni][1]);
                }
        }
        __syncthreads();
    }

    const int rq = lid >> 2, rr = (lid & 3) * 2;
    #pragma unroll
    for (int mi = 0; mi < 4; ++mi) {
        #pragma unroll
        for (int half = 0; half < 2; ++half) {
            const int m = m0 + wm * 64 + mi * 16 + rq + half * 8;
            const int bb = m >> 10, s = m & 1023;
            #pragma unroll
            for (int ni = 0; ni < 4; ++ni) {
                const int n = n0 + wn * 32 + ni * 8 + rr;
                const int h = n >> 6, d = n & 63;
                float ox = acc[mi][ni][half * 2 + 0] + bias[n];
                float oy = acc[mi][ni][half * 2 + 1] + bias[n + 1];
                __nv_bfloat16 hx = __float2bfloat16(ox);
                __nv_bfloat16 hy = __float2bfloat16(oy);
                __nv_bfloat16 lx = __float2bfloat16(ox - __bfloat162float(hx));
                __nv_bfloat16 ly = __float2bfloat16(oy - __bfloat162float(hy));
                size_t o = ((size_t)((bb * NH + h) * SQ + s)) * HD + d;
                *reinterpret_cast<__nv_bfloat162*>(&oh[o]) = __nv_bfloat162(hx, hy);
                *reinterpret_cast<__nv_bfloat162*>(&ol[o]) = __nv_bfloat162(lx, ly);
            }
        }
    }
}

// ---------------------------------------------------------------------------
// Logits + exp + rowsum: 128x128 tile per block, Q fragments in registers,
// cp.async ping-pong B tiles (Er1, Er0, K).
// Band-skip: per 16-row block at R0, only Etil cols [112-R0, 254-R0] are
// ever read by the skew gather; MMA/ldsm/stores outside are skipped.
// attn[b,h,i,j] = exp((q.k + q.Er[1023+j-i]) / 8); rowsum via atomicAdd.
// ---------------------------------------------------------------------------
#define LROW 72
#define L_PLANE (128 * LROW)                 // bf16 per plane
#define L_BUF   (2 * L_PLANE)                // 2 planes (hi+lo)
#define ES_STRIDE 260
#define L_SMEM (2 * L_BUF * 2 + 128 * ES_STRIDE * 4)   // 206848

__global__ __launch_bounds__(256, 1)
void logits_mma_kernel(float* __restrict__ attn) {
    extern __shared__ char lsm[];
    __nv_bfloat16* Bbuf = reinterpret_cast<__nv_bfloat16*>(lsm);
    float* Es = reinterpret_cast<float*>(lsm + 2 * L_BUF * 2);

    const int bh = blockIdx.z;
    const int h  = bh & 15;
    const int i0 = blockIdx.y * 128;
    const int j0 = blockIdx.x * 128;
    const int l0b = 896 + j0 - i0;           // Er row for t=0; l0b+255 <= 2047

    const __nv_bfloat16* qh = g_qh + (size_t)bh * SQ * HD;
    const __nv_bfloat16* ql = g_ql + (size_t)bh * SQ * HD;
    const __nv_bfloat16* kh = g_kh + (size_t)bh * SQ * HD;
    const __nv_bfloat16* kl = g_kl + (size_t)bh * SQ * HD;
    const __nv_bfloat16* eh = g_erh + (size_t)h * ER_L * HD;
    const __nv_bfloat16* el = g_erl + (size_t)h * ER_L * HD;

    const int tid = threadIdx.x;
    const int wid = tid >> 5;
    const int lid = tid & 31;
    const int wm = wid & 3;
    const int wn = wid >> 2;

    const int a_row = (lid & 7) + ((lid >> 3) & 1) * 8;
    const int a_kh  = (lid >= 16) ? 8 : 0;
    const int b_n   = (lid & 7) + ((lid >= 16) ? 8 : 0);
    const int b_kh  = ((lid >> 3) & 1) * 8;
    const int rq = lid >> 2, rr = (lid & 3) * 2;

    // band bounds per mi (16-row block at R0 = wm*32 + mi*16):
    // needed Etil cols t in [112-R0, 254-R0]
    const int lo0 = 112 - wm * 32,       hi0 = 254 - wm * 32;        // mi=0
    const int lo1 = 112 - wm * 32 - 16,  hi1 = 254 - wm * 32 - 16;   // mi=1

    const uint32_t sb = smem_u32(Bbuf);

    auto load_tile = [&](const __nv_bfloat16* pH, const __nv_bfloat16* pL,
                         size_t row0, int buf) {
        #pragma unroll
        for (int it = 0; it < 4; ++it) {
            int idx = tid + it * 256;            // 0..1023
            int r = idx >> 3, seg = idx & 7;     // seg: 8 bf16 = 16 B
            size_t goff = (row0 + r) * HD + seg * 8;
            uint32_t d0 = sb + (uint32_t)((buf * L_BUF + r * LROW + seg * 8) * 2);
            CP_ASYNC16(d0, pH + goff);
            CP_ASYNC16(d0 + (uint32_t)(L_PLANE * 2), pL + goff);
        }
        CP_COMMIT();
    };

    // G0: Q -> buf0  ||  G1: Er chunk1 -> buf1  (concurrent)
    load_tile(qh, ql, (size_t)i0, 0);
    load_tile(eh, el, (size_t)(l0b + 128), 1);
    CP_WAIT(1);                    // Q (G0) done; Er1 may still fly
    __syncthreads();

    uint32_t fQh[4][2][4], fQl[4][2][4];
    #pragma unroll
    for (int ks = 0; ks < 4; ++ks)
        #pragma unroll
        for (int mi = 0; mi < 2; ++mi) {
            uint32_t off = (uint32_t)(((wm * 32 + mi * 16 + a_row) * LROW
                                       + ks * 16 + a_kh) * 2);
            ldsm_x4(fQh[ks][mi], sb + off);
            ldsm_x4(fQl[ks][mi], sb + (uint32_t)(L_PLANE * 2) + off);
        }
    __syncthreads();   // everyone done reading buf0

    // G2: Er chunk0 -> buf0
    load_tile(eh, el, (size_t)l0b, 0);

    float acc[2][8][4];

    // phase 0: Er1 (buf1, Es cols 128..255)
    // phase 1: Er0 (buf0, Es cols 0..127)
    // phase 2: K   (buf1)
    #pragma unroll
    for (int phase = 0; phase < 3; ++phase) {
        if (phase < 2) CP_WAIT(1); else CP_WAIT(0);
        __syncthreads();

        const int buf = (phase == 1) ? 0 : 1;
        const uint32_t bH = sb + (uint32_t)(buf * L_BUF * 2);
        const uint32_t bL = bH + (uint32_t)(L_PLANE * 2);

        // per-tile need predicates (warp-uniform)
        const int colbase = (phase == 0) ? 128 : 0;
        bool nneed[2][8], pneed[4];
        #pragma unroll
        for (int ni = 0; ni < 8; ++ni) {
            const int c0 = colbase + wn * 64 + ni * 8;
            nneed[0][ni] = (phase == 2) || ((c0 + 7 >= lo0) && (c0 <= hi0));
            nneed[1][ni] = (phase == 2) || ((c0 + 7 >= lo1) && (c0 <= hi1));
        }
        #pragma unroll
        for (int pp = 0; pp < 4; ++pp)
            pneed[pp] = nneed[0][pp * 2] | nneed[0][pp * 2 + 1]
                      | nneed[1][pp * 2] | nneed[1][pp * 2 + 1];

        #pragma unroll
        for (int mi = 0; mi < 2; ++mi)
            #pragma unroll
            for (int ni = 0; ni < 8; ++ni)
                #pragma unroll
                for (int e = 0; e < 4; ++e) acc[mi][ni][e] = 0.f;

        #pragma unroll
        for (int ks = 0; ks < 4; ++ks) {
            const int k0 = ks * 16;
            uint32_t fBh[8][2], fBl[8][2];
            #pragma unroll
            for (int pp = 0; pp < 4; ++pp) {
                if (!pneed[pp]) continue;
                uint32_t off = (uint32_t)(((wn * 64 + pp * 16 + b_n) * LROW
                                           + k0 + b_kh) * 2);
                uint32_t t4[4];
                ldsm_x4(t4, bH + off);
                fBh[pp * 2][0] = t4[0]; fBh[pp * 2][1] = t4[1];
                fBh[pp * 2 + 1][0] = t4[2]; fBh[pp * 2 + 1][1] = t4[3];
                ldsm_x4(t4, bL + off);
                fBl[pp * 2][0] = t4[0]; fBl[pp * 2][1] = t4[1];
                fBl[pp * 2 + 1][0] = t4[2]; fBl[pp * 2 + 1][1] = t4[3];
            }
            #pragma unroll
            for (int mi = 0; mi < 2; ++mi)
                #pragma unroll
                for (int ni = 0; ni < 8; ++ni) {
                    if (!nneed[mi][ni]) continue;
                    mma_bf16(acc[mi][ni], fQh[ks][mi], fBh[ni][0], fBh[ni][1]);
                    mma_bf16(acc[mi][ni], fQh[ks][mi], fBl[ni][0], fBl[ni][1]);
                    mma_bf16(acc[mi][ni], fQl[ks][mi], fBh[ni][0], fBh[ni][1]);
                }
        }

        if (phase == 0) {
            __syncthreads();                     // all reads of buf1 done
            load_tile(kh, kl, (size_t)j0, 1);    // G3: K -> buf1
        }

        if (phase < 2) {
            #pragma unroll
            for (int mi = 0; mi < 2; ++mi)
                #pragma unroll
                for (int half = 0; half < 2; ++half) {
                    const int row = wm * 32 + mi * 16 + rq + half * 8;
                    #pragma unroll
                    for (int ni = 0; ni < 8; ++ni) {
                        if (!nneed[mi][ni]) continue;
                        const int col = colbase + wn * 64 + ni * 8 + rr;
                        *reinterpret_cast<float2*>(&Es[row * ES_STRIDE + col]) =
                            make_float2(acc[mi][ni][half * 2], acc[mi][ni][half * 2 + 1]);
                    }
                }
        }
    }

    __syncthreads();   // all Es writes visible

    // epilogue: exp + attn store + row-sum accumulation
    #pragma unroll
    for (int mi = 0; mi < 2; ++mi)
        #pragma unroll
        for (int half = 0; half < 2; ++half) {
            const int ip = wm * 32 + mi * 16 + rq + half * 8;
            const float* EsRow = Es + (size_t)ip * ES_STRIDE + (127 - ip);
            float* arow = attn + ((size_t)bh * SQ + i0 + ip) * SQ + j0;
            float rs = 0.f;
            #pragma unroll
            for (int ni = 0; ni < 8; ++ni) {
                const int jp = wn * 64 + ni * 8 + rr;
                float ex = __expf((acc[mi][ni][half * 2 + 0] + EsRow[jp])     * 0.125f);
                float ey = __expf((acc[mi][ni][half * 2 + 1] + EsRow[jp + 1]) * 0.125f);
                *reinterpret_cast<float2*>(&arow[jp]) = make_float2(ex, ey);
                rs += ex + ey;
            }
            rs += __shfl_xor_sync(0xffffffffu, rs, 1);
            rs += __shfl_xor_sync(0xffffffffu, rs, 2);
            if ((lid & 3) == 0)
                atomicAdd(&g_rowsum[(size_t)bh * SQ + i0 + ip], rs);
        }
}

// ---------------------------------------------------------------------------
// av + softmax normalization: reads exp values, normalizes in place,
// out = P_norm . v.  Block: 128 rows x 64 cols per (b,h).
// ---------------------------------------------------------------------------
#define VROW 72

__global__ __launch_bounds__(256, 2)
void av_mma_kernel(float* __restrict__ attn, float* __restrict__ out) {
    __shared__ __nv_bfloat16 Ph[128 * VROW], Pl[128 * VROW];
    __shared__ __nv_bfloat16 Vh[64 * VROW],  Vl[64 * VROW];
    __shared__ float s_inv[128];

    const int bh = blockIdx.y;
    const int b = bh >> 4, h = bh & 15;
    const int i0 = blockIdx.x * 128;
    float* ab = attn + (size_t)bh * SQ * SQ;
    const __nv_bfloat16* vh = g_vh + (size_t)bh * SQ * HD;
    const __nv_bfloat16* vl = g_vl + (size_t)bh * SQ * HD;

    const int tid = threadIdx.x;
    const int wid = tid >> 5;
    const int lid = tid & 31;
    const int wm = wid & 3;
    const int wn = wid >> 2;

    const int a_row = (lid & 7) + ((lid >> 3) & 1) * 8;
    const int a_kh  = (lid >= 16) ? 8 : 0;
    const int b_n   = (lid & 7) + ((lid >= 16) ? 8 : 0);
    const int b_kh  = ((lid >> 3) & 1) * 8;
    const int rq = lid >> 2, rr = (lid & 3) * 2;

    const uint32_t sPh = smem_u32(Ph), sPl = smem_u32(Pl);
    const uint32_t sVh = smem_u32(Vh), sVl = smem_u32(Vl);

    if (tid < 128)
        s_inv[tid] = 1.0f / g_rowsum[(size_t)bh * SQ + i0 + tid];

    float acc[2][4][4] = {};

    for (int c = 0; c < SQ / 64; ++c) {
        __syncthreads();
        // P tile: load exp values, normalize, write back, convert hi/lo
        #pragma unroll
        for (int it = 0; it < 8; ++it) {
            int idx = tid + it * 256;
            int r = idx >> 4, c4 = idx & 15;
            float* ap = ab + (size_t)(i0 + r) * SQ + c * 64 + c4 * 4;
            float4 v = *reinterpret_cast<const float4*>(ap);
            const float inv = s_inv[r];
            v.x *= inv; v.y *= inv; v.z *= inv; v.w *= inv;
            *reinterpret_cast<float4*>(ap) = v;
            uint2 H, L;
            f4_to_hilo(v, H, L);
            *reinterpret_cast<uint2*>(&Ph[r * VROW + c4 * 4]) = H;
            *reinterpret_cast<uint2*>(&Pl[r * VROW + c4 * 4]) = L;
        }
        // V tile transposed from bf16 hi/lo: smem[d][j]
        #pragma unroll
        for (int it = 0; it < 4; ++it) {
            int idx = tid + it * 256;
            int j = idx >> 4, c4 = idx & 15;
            int d0 = c4 * 4;
            size_t off = (size_t)(c * 64 + j) * HD + d0;
            union { uint2 u; __nv_bfloat16 b[4]; } hv, lv;
            hv.u = *reinterpret_cast<const uint2*>(&vh[off]);
            lv.u = *reinterpret_cast<const uint2*>(&vl[off]);
            #pragma unroll
            for (int x = 0; x < 4; ++x) {
                Vh[(d0 + x) * VROW + j] = hv.b[x];
                Vl[(d0 + x) * VROW + j] = lv.b[x];
            }
        }
        __syncthreads();

        #pragma unroll
        for (int ks = 0; ks < 4; ++ks) {
            const int k0 = ks * 16;
            uint32_t fAh[2][4], fAl[2][4], fBh[4][2], fBl[4][2];
            #pragma unroll
            for (int mi = 0; mi < 2; ++mi) {
                uint32_t off = (uint32_t)(((wm * 32 + mi * 16 + a_row) * VROW
                                           + k0 + a_kh) * 2);
                ldsm_x4(fAh[mi], sPh + off);
                ldsm_x4(fAl[mi], sPl + off);
            }
            #pragma unroll
            for (int pp = 0; pp < 2; ++pp) {
                uint32_t off = (uint32_t)(((wn * 32 + pp * 16 + b_n) * VROW
                                           + k0 + b_kh) * 2);
                uint32_t t4[4];
                ldsm_x4(t4, sVh + off);
                fBh[pp * 2][0] = t4[0]; fBh[pp * 2][1] = t4[1];
                fBh[pp * 2 + 1][0] = t4[2]; fBh[pp * 2 + 1][1] = t4[3];
                ldsm_x4(t4, sVl + off);
                fBl[pp * 2][0] = t4[0]; fBl[pp * 2][1] = t4[1];
                fBl[pp * 2 + 1][0] = t4[2]; fBl[pp * 2 + 1][1] = t4[3];
            }
            #pragma unroll
            for (int mi = 0; mi < 2; ++mi)
                #pragma unroll
                for (int ni = 0; ni < 4; ++ni) {
                    mma_bf16(acc[mi][ni], fAh[mi], fBh[ni][0], fBh[ni][1]);
                    mma_bf16(acc[mi][ni], fAh[mi], fBl[ni][0], fBl[ni][1]);
                    mma_bf16(acc[mi][ni], fAl[mi], fBh[ni][0], fBh[ni][1]);
                }
        }
    }

    #pragma unroll
    for (int mi = 0; mi < 2; ++mi)
        #pragma unroll
        for (int half = 0; half < 2; ++half) {
            const int s = i0 + wm * 32 + mi * 16 + rq + half * 8;
            #pragma unroll
            for (int ni = 0; ni < 4; ++ni) {
                const int d = wn * 32 + ni * 8 + rr;
                float2 o;
                o.x = acc[mi][ni][half * 2 + 0];
                o.y = acc[mi][ni][half * 2 + 1];
                *reinterpret_cast<float2*>(
                    &out[((size_t)(b * SQ + s)) * DM + h * HD + d]) = o;
            }
        }
}

// ---------------------------------------------------------------------------
extern "C" void kernel_launch(void* const* d_in, const int* in_sizes, int n_in,
                              void* d_out, int out_size) {
    const float* query = (const float*)d_in[0];
    const float* key   = (const float*)d_in[1];
    const float* value = (const float*)d_in[2];
    const float* Wq    = (const float*)d_in[3];
    const float* bq    = (const float*)d_in[4];
    const float* Wk    = (const float*)d_in[5];
    const float* bk    = (const float*)d_in[6];
    const float* Wv    = (const float*)d_in[7];
    const float* bv    = (const float*)d_in[8];
    const float* Er    = (const float*)d_in[9];

    float* out  = (float*)d_out;                       // (4,1024,1024)
    float* attn = out + (size_t)NB * SQ * DM;          // (4,16,1024,1024)

    cudaFuncSetAttribute(logits_mma_kernel,
                         cudaFuncAttributeMaxDynamicSharedMemorySize, L_SMEM);
    cudaFuncSetAttribute(proj_mma_kernel,
                         cudaFuncAttributeMaxDynamicSharedMemorySize, P_SMEM);

    const int en4 = NH * ER_L * HD / 4;
    split_all_kernel<<<(SPLIT_TOTAL + 255) / 256, 256>>>(query, key, value, Wq, Wk, Wv);
    er_split_kernel<<<(en4 + 255) / 256, 256>>>(Er, en4);
    zero_rowsum_kernel<<<BH, 1024>>>();

    dim3 pg(DM / 128, NB * SQ / 128, 3);               // (8, 32, 3)
    proj_mma_kernel<<<pg, 256, P_SMEM>>>(bq, bk, bv);

    dim3 lg(SQ / 128, SQ / 128, BH);                   // (8, 8, 64)
    logits_mma_kernel<<<lg, 256, L_SMEM>>>(attn);

    dim3 ag(SQ / 128, BH);                             // (8, 64)
    av_mma_kernel<<<ag, 256>>>(attn, out);
}